// round 13
// baseline (speedup 1.0000x reference)
#include <cuda_runtime.h>
#include <math.h>

// Persistent-CTA version of the R8 pipeline: grid = 888 CTAs (148 SMs x 6),
// each CTA loops over row-groups (4 rows/group) strided by gridDim with
// DOUBLE-BUFFERED cp.async staging: group g+1's 4 loads are issued into the
// alternate 16KB buffer before group g is processed, so the async queue
// never drains (up to 8 commit-groups in flight; wait_group 7-r retires
// exactly group g's row r while keeping g+1 pending). Removes the per-CTA
// cold-pipeline refill bubble and wave-transition overhead of the 32768-CTA
// launch. Ballot-based stable compaction, w/b register-resident, streaming
// __stcs stores.

#define SIZE 1024
#define THREADS 256
#define ROWS 4
#define GROUP_BYTES (ROWS * SIZE * 4)

__global__ __launch_bounds__(THREADS, 6)
void nan_dense_kernel(const float* __restrict__ X,
                      const float4* __restrict__ w4,
                      const float4* __restrict__ b4,
                      float4* __restrict__ out4,
                      int ngroups)
{
    __shared__ float raw[2][ROWS * SIZE];   // 32 KB double-buffered staging
    __shared__ float cmp[SIZE];             // 4 KB compaction buffer
    __shared__ int wtot[8];

    const int t    = threadIdx.x;
    const int lane = t & 31;
    const int wid  = t >> 5;
    const int V    = SIZE / 4;

    const unsigned raw_sa = (unsigned)__cvta_generic_to_shared(raw) + (t << 4);
    const float4 wv = __ldg(&w4[t]);
    const float4 bv = __ldg(&b4[t]);
    const unsigned lt = (1u << lane) - 1u;
    const int base = t << 2;

    int g = blockIdx.x;
    if (g >= ngroups) return;

    // Prologue: issue group g into buffer 0.
    {
        const float* src = X + (long long)g * ROWS * SIZE + (t << 2);
#pragma unroll
        for (int r = 0; r < ROWS; ++r) {
            asm volatile(
                "cp.async.cg.shared.global [%0], [%1], 16;\n\t"
                "cp.async.commit_group;\n"
                :: "r"(raw_sa + r * (SIZE * 4)), "l"(src + r * SIZE)
                : "memory");
        }
    }

    int buf = 0;
    while (true) {
        const int gn = g + gridDim.x;
        const bool has_next = gn < ngroups;

        // Issue next group's loads into the alternate buffer (queue stays full).
        if (has_next) {
            const float* src = X + (long long)gn * ROWS * SIZE + (t << 2);
            const unsigned dst = raw_sa + (unsigned)(buf ^ 1) * GROUP_BYTES;
#pragma unroll
            for (int r = 0; r < ROWS; ++r) {
                asm volatile(
                    "cp.async.cg.shared.global [%0], [%1], 16;\n\t"
                    "cp.async.commit_group;\n"
                    :: "r"(dst + r * (SIZE * 4)), "l"(src + r * SIZE)
                    : "memory");
            }
        }

        const long long r0 = (long long)g * ROWS;
        const float* rbuf = raw[buf];

#pragma unroll
        for (int r = 0; r < ROWS; ++r) {
            // Retire exactly group g's row r; keep g+1's groups pending.
            if (has_next) {
                switch (r) {
                    case 0: asm volatile("cp.async.wait_group 7;" ::: "memory"); break;
                    case 1: asm volatile("cp.async.wait_group 6;" ::: "memory"); break;
                    case 2: asm volatile("cp.async.wait_group 5;" ::: "memory"); break;
                    default: asm volatile("cp.async.wait_group 4;" ::: "memory"); break;
                }
            } else {
                switch (r) {
                    case 0: asm volatile("cp.async.wait_group 3;" ::: "memory"); break;
                    case 1: asm volatile("cp.async.wait_group 2;" ::: "memory"); break;
                    case 2: asm volatile("cp.async.wait_group 1;" ::: "memory"); break;
                    default: asm volatile("cp.async.wait_group 0;" ::: "memory"); break;
                }
            }

            // Read back own 16 bytes (written by this thread's own cp.async).
            const float4 cur = reinterpret_cast<const float4*>(rbuf)[r * V + t];
            float v[4] = {cur.x, cur.y, cur.z, cur.w};

            int pre = 0, wt = 0;
#pragma unroll
            for (int k = 0; k < 4; ++k) {
                const unsigned m = __ballot_sync(0xffffffffu, isfinite(v[k]));
                pre += __popc(m & lt);
                wt  += __popc(m);
            }
            if (lane == 0) wtot[wid] = wt;
            __syncthreads();   // wtot visible; orders prev row's cmp reads

            int off = 0, total = 0;
#pragma unroll
            for (int i = 0; i < 8; ++i) {
                const int ti = wtot[i];
                total += ti;
                if (i < wid) off += ti;
            }

            int pos = off + pre;
#pragma unroll
            for (int k = 0; k < 4; ++k) {
                if (isfinite(v[k])) cmp[pos++] = v[k];
            }
            __syncthreads();   // scatter complete

            const float4 sv = reinterpret_cast<const float4*>(cmp)[t];
            float4 o;
            o.x = (base + 0 < total) ? fmaf(sv.x, wv.x, bv.x) : 0.0f;
            o.y = (base + 1 < total) ? fmaf(sv.y, wv.y, bv.y) : 0.0f;
            o.z = (base + 2 < total) ? fmaf(sv.z, wv.z, bv.z) : 0.0f;
            o.w = (base + 3 < total) ? fmaf(sv.w, wv.w, bv.w) : 0.0f;

            __stcs(&out4[(r0 + r) * V + t], o);
        }

        if (!has_next) break;
        g = gn;
        buf ^= 1;
    }
}

extern "C" void kernel_launch(void* const* d_in, const int* in_sizes, int n_in,
                              void* d_out, int out_size)
{
    const float* X = (const float*)d_in[0];
    const float* w = (const float*)d_in[1];
    const float* b = (const float*)d_in[2];
    float* out = (float*)d_out;

    const int batch   = in_sizes[0] / SIZE;        // 131072
    const int ngroups = batch / ROWS;              // 32768
    const int grid    = 148 * 6;                   // persistent: 6 CTAs/SM

    nan_dense_kernel<<<grid, THREADS>>>(
        X,
        reinterpret_cast<const float4*>(w),
        reinterpret_cast<const float4*>(b),
        reinterpret_cast<float4*>(out),
        ngroups);
}

// round 14
// speedup vs baseline: 1.2591x; 1.2591x over previous
#include <cuda_runtime.h>
#include <math.h>

// FINAL — R8 structure, best measured configuration (156.1us bench,
// 153.0us ncu window, DRAM 83.9%, HBM 6.65 TB/s). Confirmed at the mixed
// read/write HBM3e efficiency ceiling by five structurally distinct
// variants (occ 58-92%, MLP 1-4, 1-2 barriers/row, persistent and
// launch-per-group): all plateau at 6.5-6.7 TB/s.
//
// Structure: 256 threads/CTA, 4 rows per CTA. All 4 rows staged
// global->shared via cp.async.cg (register-free MLP, no L1 allocation),
// one commit group per row; rows processed one at a time (wait_group 3-r
// overlaps row r's compute with rows r+1.. still in flight). Only 4 row
// floats live at a time -> 40 regs -> 6 CTAs/SM. Each thread reads back
// only the bytes its own cp.async wrote, so no sync between wait and
// readback. Ballot-based stable compaction (popc-prefix over per-element
// ballots; element-major order matches the original 4t+k index, so the
// compaction is stable). w/b register-resident (one broadcast load per
// CTA); __stcs streaming stores keep L2 clean for the read stream.

#define SIZE 1024
#define THREADS 256
#define ROWS 4

__global__ __launch_bounds__(THREADS, 6)
void nan_dense_kernel(const float* __restrict__ X,
                      const float4* __restrict__ w4,
                      const float4* __restrict__ b4,
                      float4* __restrict__ out4)
{
    __shared__ float raw[ROWS * SIZE];      // 16 KB staging
    __shared__ float cmp[SIZE];             // 4 KB compaction buffer
    __shared__ int wtot[8];

    const int t    = threadIdx.x;
    const int lane = t & 31;
    const int wid  = t >> 5;
    const int V    = SIZE / 4;

    const long long r0 = (long long)blockIdx.x * ROWS;
    const float* gsrc = X + r0 * SIZE + (t << 2);
    const unsigned raw_sa = (unsigned)__cvta_generic_to_shared(raw) + (t << 4);

    // Stage all four rows; one commit group per row (FIFO retirement).
#pragma unroll
    for (int r = 0; r < ROWS; ++r) {
        asm volatile(
            "cp.async.cg.shared.global [%0], [%1], 16;\n\t"
            "cp.async.commit_group;\n"
            :: "r"(raw_sa + r * (SIZE * 4)), "l"(gsrc + r * SIZE)
            : "memory");
    }

    const float4 wv = __ldg(&w4[t]);
    const float4 bv = __ldg(&b4[t]);
    const unsigned lt = (1u << lane) - 1u;
    const int base = t << 2;

#pragma unroll
    for (int r = 0; r < ROWS; ++r) {
        // Wait until this row's group has landed (groups retire in order).
        switch (r) {
            case 0: asm volatile("cp.async.wait_group 3;" ::: "memory"); break;
            case 1: asm volatile("cp.async.wait_group 2;" ::: "memory"); break;
            case 2: asm volatile("cp.async.wait_group 1;" ::: "memory"); break;
            default: asm volatile("cp.async.wait_group 0;" ::: "memory"); break;
        }

        // Read back own 16 bytes (written by this thread's own cp.async).
        const float4 cur = reinterpret_cast<const float4*>(raw)[r * V + t];
        float v[4] = {cur.x, cur.y, cur.z, cur.w};

        int pre = 0, wt = 0;
#pragma unroll
        for (int k = 0; k < 4; ++k) {
            const unsigned m = __ballot_sync(0xffffffffu, isfinite(v[k]));
            pre += __popc(m & lt);
            wt  += __popc(m);
        }
        if (lane == 0) wtot[wid] = wt;
        __syncthreads();   // wtot visible; also orders prev row's cmp reads

        int off = 0, total = 0;
#pragma unroll
        for (int i = 0; i < 8; ++i) {
            const int ti = wtot[i];
            total += ti;
            if (i < wid) off += ti;
        }

        int pos = off + pre;
#pragma unroll
        for (int k = 0; k < 4; ++k) {
            if (isfinite(v[k])) cmp[pos++] = v[k];
        }
        __syncthreads();   // scatter complete

        const float4 sv = reinterpret_cast<const float4*>(cmp)[t];
        float4 o;
        o.x = (base + 0 < total) ? fmaf(sv.x, wv.x, bv.x) : 0.0f;
        o.y = (base + 1 < total) ? fmaf(sv.y, wv.y, bv.y) : 0.0f;
        o.z = (base + 2 < total) ? fmaf(sv.z, wv.z, bv.z) : 0.0f;
        o.w = (base + 3 < total) ? fmaf(sv.w, wv.w, bv.w) : 0.0f;

        __stcs(&out4[(r0 + r) * V + t], o);
    }
}

extern "C" void kernel_launch(void* const* d_in, const int* in_sizes, int n_in,
                              void* d_out, int out_size)
{
    const float* X = (const float*)d_in[0];
    const float* w = (const float*)d_in[1];
    const float* b = (const float*)d_in[2];
    float* out = (float*)d_out;

    const int batch = in_sizes[0] / SIZE;   // 131072 (multiple of 4)
    nan_dense_kernel<<<batch / ROWS, THREADS>>>(
        X,
        reinterpret_cast<const float4*>(w),
        reinterpret_cast<const float4*>(b),
        reinterpret_cast<float4*>(out));
}

// round 15
// speedup vs baseline: 1.2647x; 1.0045x over previous
#include <cuda_runtime.h>
#include <math.h>

// R8 structure (confirmed best, 156.1us / DRAM 83.9%) + L2 evict-first
// policy on the cp.async READ stream (symmetric to the proven __stcs
// evict-first on the write stream): X lines are zero-reuse, marking them
// evict_first keeps L2 ways available for the outgoing write stream.
//
// 256 threads/CTA, 4 rows staged via cp.async.cg (register-free MLP),
// one commit group per row, wait_group 3-r overlaps row r compute with
// rows r+1.. in flight. Ballot-based stable compaction; w/b
// register-resident; __stcs streaming stores.

#define SIZE 1024
#define THREADS 256
#define ROWS 4

__global__ __launch_bounds__(THREADS, 6)
void nan_dense_kernel(const float* __restrict__ X,
                      const float4* __restrict__ w4,
                      const float4* __restrict__ b4,
                      float4* __restrict__ out4)
{
    __shared__ float raw[ROWS * SIZE];      // 16 KB staging
    __shared__ float cmp[SIZE];             // 4 KB compaction buffer
    __shared__ int wtot[8];

    const int t    = threadIdx.x;
    const int lane = t & 31;
    const int wid  = t >> 5;
    const int V    = SIZE / 4;

    const long long r0 = (long long)blockIdx.x * ROWS;
    const float* gsrc = X + r0 * SIZE + (t << 2);
    const unsigned raw_sa = (unsigned)__cvta_generic_to_shared(raw) + (t << 4);

    // Evict-first policy for the zero-reuse read stream.
    unsigned long long pol;
    asm volatile("createpolicy.fractional.L2::evict_first.b64 %0, 1.0;"
                 : "=l"(pol));

    // Stage all four rows; one commit group per row (FIFO retirement).
#pragma unroll
    for (int r = 0; r < ROWS; ++r) {
        asm volatile(
            "cp.async.cg.shared.global.L2::cache_hint [%0], [%1], 16, %2;\n\t"
            "cp.async.commit_group;\n"
            :: "r"(raw_sa + r * (SIZE * 4)), "l"(gsrc + r * SIZE), "l"(pol)
            : "memory");
    }

    const float4 wv = __ldg(&w4[t]);
    const float4 bv = __ldg(&b4[t]);
    const unsigned lt = (1u << lane) - 1u;
    const int base = t << 2;

#pragma unroll
    for (int r = 0; r < ROWS; ++r) {
        // Wait until this row's group has landed (groups retire in order).
        switch (r) {
            case 0: asm volatile("cp.async.wait_group 3;" ::: "memory"); break;
            case 1: asm volatile("cp.async.wait_group 2;" ::: "memory"); break;
            case 2: asm volatile("cp.async.wait_group 1;" ::: "memory"); break;
            default: asm volatile("cp.async.wait_group 0;" ::: "memory"); break;
        }

        // Read back own 16 bytes (written by this thread's own cp.async).
        const float4 cur = reinterpret_cast<const float4*>(raw)[r * V + t];
        float v[4] = {cur.x, cur.y, cur.z, cur.w};

        int pre = 0, wt = 0;
#pragma unroll
        for (int k = 0; k < 4; ++k) {
            const unsigned m = __ballot_sync(0xffffffffu, isfinite(v[k]));
            pre += __popc(m & lt);
            wt  += __popc(m);
        }
        if (lane == 0) wtot[wid] = wt;
        __syncthreads();   // wtot visible; also orders prev row's cmp reads

        int off = 0, total = 0;
#pragma unroll
        for (int i = 0; i < 8; ++i) {
            const int ti = wtot[i];
            total += ti;
            if (i < wid) off += ti;
        }

        int pos = off + pre;
#pragma unroll
        for (int k = 0; k < 4; ++k) {
            if (isfinite(v[k])) cmp[pos++] = v[k];
        }
        __syncthreads();   // scatter complete

        const float4 sv = reinterpret_cast<const float4*>(cmp)[t];
        float4 o;
        o.x = (base + 0 < total) ? fmaf(sv.x, wv.x, bv.x) : 0.0f;
        o.y = (base + 1 < total) ? fmaf(sv.y, wv.y, bv.y) : 0.0f;
        o.z = (base + 2 < total) ? fmaf(sv.z, wv.z, bv.z) : 0.0f;
        o.w = (base + 3 < total) ? fmaf(sv.w, wv.w, bv.w) : 0.0f;

        __stcs(&out4[(r0 + r) * V + t], o);
    }
}

extern "C" void kernel_launch(void* const* d_in, const int* in_sizes, int n_in,
                              void* d_out, int out_size)
{
    const float* X = (const float*)d_in[0];
    const float* w = (const float*)d_in[1];
    const float* b = (const float*)d_in[2];
    float* out = (float*)d_out;

    const int batch = in_sizes[0] / SIZE;   // 131072 (multiple of 4)
    nan_dense_kernel<<<batch / ROWS, THREADS>>>(
        X,
        reinterpret_cast<const float4*>(w),
        reinterpret_cast<const float4*>(b),
        reinterpret_cast<float4*>(out));
}